// round 1
// baseline (speedup 1.0000x reference)
#include <cuda_runtime.h>

#define P_DIM 512
#define Q_DIM 64
#define B_DIM 16
#define E_DIM 256
#define H_DIM 256
#define O_DIM 256

// ---------------- scratch (static __device__, no allocation) ----------------
__device__ float g_Wp[P_DIM * B_DIM * H_DIM];          // (P,B,H)
__device__ float g_Wq[Q_DIM * B_DIM * H_DIM];          // (Q,B,H)
__device__ float g_gcat[P_DIM * B_DIM * 2 * E_DIM];    // (P,B,2E) = [passage | c]
__device__ float g_cg[P_DIM * B_DIM * E_DIM];          // c_gated
__device__ float g_gi[P_DIM * B_DIM * 3 * O_DIM];      // gi = x@w_ih^T + b_ih

// ---------------- math helpers ----------------
__device__ __forceinline__ float fast_tanh(float x) {
    float e = __expf(2.f * x);
    return 1.f - __fdividef(2.f, e + 1.f);
}
__device__ __forceinline__ float fast_sigmoid(float x) {
    return __fdividef(1.f, 1.f + __expf(-x));
}
__device__ __forceinline__ unsigned smem_u32(const void* p) {
    return (unsigned)__cvta_generic_to_shared(p);
}

// ---------------- generic fp32 GEMM: C[M,N] = epi(A[M,K] @ W[N,K]^T) ----------------
// MODE 0: raw    MODE 1: + bias[n]    MODE 2: sigmoid(acc) * aux[row*512 + 256 + n]
// All dims are multiples of 64 (M), 64 (N), 32 (K) here: no bounds checks.
template <int MODE>
__global__ __launch_bounds__(256) void gemm_kernel(
    const float* __restrict__ A, const float* __restrict__ W,
    const float* __restrict__ bias, const float* __restrict__ aux,
    float* __restrict__ C, int M, int N, int K)
{
    __shared__ float As[32 * 68];   // [k][m], padded stride 68
    __shared__ float Ws[32 * 68];   // [k][n]

    const int tid = threadIdx.x;
    const int m0 = blockIdx.x * 64;
    const int n0 = blockIdx.y * 64;
    const int tm = tid >> 4;   // 0..15
    const int tn = tid & 15;   // 0..15
    const int K4 = K >> 2;

    float acc[4][4];
#pragma unroll
    for (int i = 0; i < 4; i++)
#pragma unroll
        for (int j = 0; j < 4; j++) acc[i][j] = 0.f;

    const float4* A4 = (const float4*)A;
    const float4* W4 = (const float4*)W;

    for (int k0 = 0; k0 < K; k0 += 32) {
#pragma unroll
        for (int t = 0; t < 2; t++) {
            int idx = tid + t * 256;          // 0..511
            int r = idx >> 3;                 // 0..63
            int c4 = idx & 7;                 // 0..7  (float4 within 32-wide K tile)
            float4 va = A4[(long)(m0 + r) * K4 + (k0 >> 2) + c4];
            float4 vw = W4[(long)(n0 + r) * K4 + (k0 >> 2) + c4];
            int kk = c4 * 4;
            As[(kk + 0) * 68 + r] = va.x; As[(kk + 1) * 68 + r] = va.y;
            As[(kk + 2) * 68 + r] = va.z; As[(kk + 3) * 68 + r] = va.w;
            Ws[(kk + 0) * 68 + r] = vw.x; Ws[(kk + 1) * 68 + r] = vw.y;
            Ws[(kk + 2) * 68 + r] = vw.z; Ws[(kk + 3) * 68 + r] = vw.w;
        }
        __syncthreads();

        const float4* As4 = (const float4*)As;   // row k at k*17 float4
        const float4* Ws4 = (const float4*)Ws;
#pragma unroll
        for (int k = 0; k < 32; k++) {
            float4 a = As4[k * 17 + tm];
            float4 w = Ws4[k * 17 + tn];
            acc[0][0] += a.x * w.x; acc[0][1] += a.x * w.y; acc[0][2] += a.x * w.z; acc[0][3] += a.x * w.w;
            acc[1][0] += a.y * w.x; acc[1][1] += a.y * w.y; acc[1][2] += a.y * w.z; acc[1][3] += a.y * w.w;
            acc[2][0] += a.z * w.x; acc[2][1] += a.z * w.y; acc[2][2] += a.z * w.z; acc[2][3] += a.z * w.w;
            acc[3][0] += a.w * w.x; acc[3][1] += a.w * w.y; acc[3][2] += a.w * w.z; acc[3][3] += a.w * w.w;
        }
        __syncthreads();
    }

#pragma unroll
    for (int i = 0; i < 4; i++) {
        int row = m0 + tm * 4 + i;
        int col = n0 + tn * 4;
        float4 o;
        if (MODE == 0) {
            o = make_float4(acc[i][0], acc[i][1], acc[i][2], acc[i][3]);
        } else if (MODE == 1) {
            o = make_float4(acc[i][0] + bias[col + 0], acc[i][1] + bias[col + 1],
                            acc[i][2] + bias[col + 2], acc[i][3] + bias[col + 3]);
        } else {
            float4 g = *(const float4*)(aux + (long)row * 512 + 256 + col);
            o = make_float4(fast_sigmoid(acc[i][0]) * g.x, fast_sigmoid(acc[i][1]) * g.y,
                            fast_sigmoid(acc[i][2]) * g.z, fast_sigmoid(acc[i][3]) * g.w);
        }
        *(float4*)(&C[(long)row * N + col]) = o;
    }
}

// ---------------- fused attention: scores -> softmax -> context -> concat ----------------
// block = (p, b), 256 threads (8 warps). Writes g_gcat[p,b,0:256]=passage, [256:512]=c.
__global__ __launch_bounds__(256) void attn_kernel(
    const float* __restrict__ question, const float* __restrict__ passage,
    const float* __restrict__ v)
{
    __shared__ float wp[256];
    __shared__ float vv[256];
    __shared__ float sc[64];

    const int p = blockIdx.x;
    const int b = blockIdx.y;
    const int tid = threadIdx.x;
    const int w = tid >> 5, l = tid & 31;

    wp[tid] = g_Wp[((long)p * B_DIM + b) * H_DIM + tid];
    vv[tid] = v[tid];
    __syncthreads();

    // scores[q] = sum_h v[h] * tanh(Wq[q,b,h] + Wp[p,b,h]); warp w handles q = w*8 .. w*8+7
#pragma unroll
    for (int qi = 0; qi < 8; qi++) {
        int q = w * 8 + qi;
        const float* wq = &g_Wq[((long)q * B_DIM + b) * H_DIM];
        float acc = 0.f;
#pragma unroll
        for (int j = 0; j < 8; j++) {
            int h = l + 32 * j;
            acc += vv[h] * fast_tanh(wq[h] + wp[h]);
        }
#pragma unroll
        for (int s = 16; s > 0; s >>= 1) acc += __shfl_xor_sync(0xffffffffu, acc, s);
        if (l == 0) sc[q] = acc;
    }
    __syncthreads();

    // softmax over q (64) by warp 0
    if (w == 0) {
        float s0 = sc[l], s1 = sc[32 + l];
        float m = fmaxf(s0, s1);
#pragma unroll
        for (int s = 16; s > 0; s >>= 1) m = fmaxf(m, __shfl_xor_sync(0xffffffffu, m, s));
        float e0 = __expf(s0 - m), e1 = __expf(s1 - m);
        float sum = e0 + e1;
#pragma unroll
        for (int s = 16; s > 0; s >>= 1) sum += __shfl_xor_sync(0xffffffffu, sum, s);
        float inv = __fdividef(1.f, sum);
        sc[l] = e0 * inv;
        sc[32 + l] = e1 * inv;
    }
    __syncthreads();

    // context c[p,b,e] = sum_q a[q] * question[q,b,e]; thread = e
    float acc = 0.f;
#pragma unroll
    for (int q = 0; q < 64; q++)
        acc += sc[q] * question[((long)q * B_DIM + b) * E_DIM + tid];

    float* gr = &g_gcat[((long)p * B_DIM + b) * 2 * E_DIM];
    gr[256 + tid] = acc;
    gr[tid] = passage[((long)p * B_DIM + b) * E_DIM + tid];
}

// ---------------- GRU: 8-CTA cluster per batch, w_hh slice in registers ----------------
__device__ __forceinline__ void cluster_sync_all() {
    asm volatile("barrier.cluster.arrive.aligned;" ::: "memory");
    asm volatile("barrier.cluster.wait.aligned;" ::: "memory");
}

__global__ void __cluster_dims__(8, 1, 1) __launch_bounds__(384)
gru_kernel(const float* __restrict__ gi, const float* __restrict__ w_hh,
           const float* __restrict__ b_hh, float* __restrict__ out)
{
    // h buffers padded: slot for output o at (o>>6)*68 + (o&63); double-buffered
    __shared__ float hb[2][4 * 68];
    __shared__ float ghs[96];
    __shared__ float bhh_s[96];

    const int tid = threadIdx.x;
    const int b = blockIdx.x >> 3;     // batch
    const int rank = blockIdx.x & 7;   // cluster rank
    const int rloc = tid >> 2;         // local row 0..95
    const int q = tid & 3;             // K-slice 0..3 (64 each)
    const int gate = rloc >> 5;        // 0=r,1=z,2=n
    const int oc = rloc & 31;          // output within chunk
    const int grow = gate * 256 + rank * 32 + oc;   // global w_hh row

    // preload this thread's 64 weights
    float4 wv[16];
    const float4* wg4 = (const float4*)(w_hh + (long)grow * 256 + q * 64);
#pragma unroll
    for (int i = 0; i < 16; i++) wv[i] = wg4[i];

    if (tid < 96) bhh_s[tid] = b_hh[(tid >> 5) * 256 + rank * 32 + (tid & 31)];
    for (int i = tid; i < 2 * 4 * 68; i += 384) ((float*)hb)[i] = 0.f;
    __syncthreads();
    cluster_sync_all();   // all CTAs initialized before any remote h writes

    for (int p = 0; p < P_DIM; p++) {
        const int cur = p & 1;
        const int nxt = cur ^ 1;

        // prefetch gi for this step (warp 0 consumes in gate phase)
        float gir = 0.f, giz = 0.f, gin = 0.f;
        if (tid < 32) {
            long base = ((long)p * B_DIM + b) * 768 + rank * 32 + tid;
            gir = gi[base];
            giz = gi[base + 256];
            gin = gi[base + 512];
        }

        // gh[row] = sum_k h[k] * w_hh[row][k], split over 4 lanes in K
        const float4* h4 = (const float4*)hb[cur];
        float a0 = 0.f, a1 = 0.f, a2 = 0.f, a3 = 0.f;
#pragma unroll
        for (int i = 0; i < 16; i++) {
            float4 hv = h4[q * 17 + i];
            a0 += wv[i].x * hv.x;
            a1 += wv[i].y * hv.y;
            a2 += wv[i].z * hv.z;
            a3 += wv[i].w * hv.w;
        }
        float acc = (a0 + a1) + (a2 + a3);
        acc += __shfl_xor_sync(0xffffffffu, acc, 1);
        acc += __shfl_xor_sync(0xffffffffu, acc, 2);
        if (q == 0) ghs[rloc] = acc;
        __syncthreads();

        if (tid < 32) {
            int o = rank * 32 + tid;
            float ghr = ghs[tid]      + bhh_s[tid];
            float ghz = ghs[32 + tid] + bhh_s[32 + tid];
            float ghn = ghs[64 + tid] + bhh_s[64 + tid];
            float r = fast_sigmoid(gir + ghr);
            float z = fast_sigmoid(giz + ghz);
            float n = fast_tanh(gin + r * ghn);
            float hold = hb[cur][(o >> 6) * 68 + (o & 63)];
            float hnew = (1.f - z) * n + z * hold;
            out[((long)p * B_DIM + b) * O_DIM + o] = hnew;

            // broadcast h_new chunk to every CTA in the cluster (incl. self)
            unsigned laddr = smem_u32(&hb[nxt][(o >> 6) * 68 + (o & 63)]);
#pragma unroll
            for (int c2 = 0; c2 < 8; c2++) {
                unsigned raddr;
                asm("mapa.shared::cluster.u32 %0, %1, %2;" : "=r"(raddr) : "r"(laddr), "r"(c2));
                asm volatile("st.shared::cluster.f32 [%0], %1;" :: "r"(raddr), "f"(hnew));
            }
        }
        cluster_sync_all();   // release DSMEM stores / acquire peers' h
    }
}

// ---------------- launch ----------------
extern "C" void kernel_launch(void* const* d_in, const int* in_sizes, int n_in,
                              void* d_out, int out_size)
{
    const float* passage  = (const float*)d_in[0];
    const float* question = (const float*)d_in[1];
    const float* Wuq      = (const float*)d_in[2];
    const float* Wup      = (const float*)d_in[3];
    const float* v        = (const float*)d_in[4];
    const float* Wg       = (const float*)d_in[5];
    const float* w_ih     = (const float*)d_in[6];
    const float* w_hh     = (const float*)d_in[7];
    const float* b_ih     = (const float*)d_in[8];
    const float* b_hh     = (const float*)d_in[9];
    float* out = (float*)d_out;

    void *pWp, *pWq, *pGcat, *pCg, *pGi;
    cudaGetSymbolAddress(&pWp, g_Wp);
    cudaGetSymbolAddress(&pWq, g_Wq);
    cudaGetSymbolAddress(&pGcat, g_gcat);
    cudaGetSymbolAddress(&pCg, g_cg);
    cudaGetSymbolAddress(&pGi, g_gi);

    dim3 blk(256);

    // Wp = passage @ Wup^T : (8192,256)@(256,256)^T
    gemm_kernel<0><<<dim3(8192 / 64, 256 / 64), blk>>>(
        passage, Wup, nullptr, nullptr, (float*)pWp, 8192, 256, 256);
    // Wq = question @ Wuq^T : (1024,256)@(256,256)^T
    gemm_kernel<0><<<dim3(1024 / 64, 256 / 64), blk>>>(
        question, Wuq, nullptr, nullptr, (float*)pWq, 1024, 256, 256);
    // attention + softmax + context + concat
    attn_kernel<<<dim3(P_DIM, B_DIM), blk>>>(question, passage, v);
    // c_gated = sigmoid(gcat @ Wg[256:512,:]^T) * c : (8192,256), K=512
    gemm_kernel<2><<<dim3(8192 / 64, 256 / 64), blk>>>(
        (const float*)pGcat, Wg + 256 * 512, nullptr, (const float*)pGcat,
        (float*)pCg, 8192, 256, 512);
    // gi = c_gated @ w_ih^T + b_ih : (8192,768)
    gemm_kernel<1><<<dim3(8192 / 64, 768 / 64), blk>>>(
        (const float*)pCg, w_ih, b_ih, nullptr, (float*)pGi, 8192, 768, 256);
    // GRU recurrence: 16 clusters of 8 CTAs (one per batch)
    gru_kernel<<<128, 384>>>((const float*)pGi, w_hh, b_hh, out);
}